// round 12
// baseline (speedup 1.0000x reference)
#include <cuda_runtime.h>
#include <cuda_bf16.h>
#include <cstdint>

// Problem shape (fixed)
#define BB_ 64
#define SS_ 512
#define HH_ 1024
#define LL_ 9

#define TPB 256
#define WARPS 8
#define ROWS_PER_BLOCK 128
#define NCHUNK 16               // 512/32 mask chunks
#define NR (BB_ * SS_)          // 32768 rows

typedef unsigned long long u64;

// W packed as j-pairs per k: g_Wpack[k*5 + jp] = (W[k][2jp], W[k][2jp+1]), jp=4 -> (W[k][8], 0)
__device__ u64 g_Wpack[HH_ * 5];          // 40 KB
// split-K partials: [slice(8)][jp(5)][row] as f32x2 pairs
__device__ u64 g_part[8 * 5 * NR];        // 10.5 MB
__device__ int g_nvalid[BB_];

__device__ __forceinline__ u64 fma2(u64 a, u64 b, u64 c) {
    u64 d;
    asm("fma.rn.f32x2 %0, %1, %2, %3;" : "=l"(d) : "l"(a), "l"(b), "l"(c));
    return d;
}
__device__ __forceinline__ u64 add2(u64 a, u64 b) {
    u64 d;
    asm("add.rn.f32x2 %0, %1, %2;" : "=l"(d) : "l"(a), "l"(b));
    return d;
}
__device__ __forceinline__ u64 pack2(float lo, float hi) {
    u64 d;
    asm("mov.b64 %0, {%1, %2};" : "=l"(d) : "f"(lo), "f"(hi));
    return d;
}
__device__ __forceinline__ void unpack2(float& lo, float& hi, u64 v) {
    asm("mov.b64 {%0, %1}, %2;" : "=f"(lo), "=f"(hi) : "l"(v));
}

// ---------------------------------------------------------------------------
// One-shot: W [H,L] row-major -> g_Wpack (j-pairs per k)
// ---------------------------------------------------------------------------
__global__ void pack_W(const float* __restrict__ W) {
    int k = blockIdx.x * 256 + threadIdx.x;   // 0..1023
    #pragma unroll
    for (int jp = 0; jp < 4; jp++)
        g_Wpack[k * 5 + jp] = pack2(W[k * LL_ + 2 * jp], W[k * LL_ + 2 * jp + 1]);
    g_Wpack[k * 5 + 4] = pack2(W[k * LL_ + 8], 0.0f);
}

// ---------------------------------------------------------------------------
// Kernel 1: W-stationary split-K GEMV partials.
// Block = 128 rows of one batch. Thread t owns k in [4t, 4t+4) with W in regs.
// Per row: one coalesced block-wide LDG.128 of the full 4KB row, 20 fma2,
// butterfly reduce (5 f32x2 chains), 40B partial store per warp.
// ---------------------------------------------------------------------------
__global__ __launch_bounds__(TPB, 3)
void gemv_partial_kernel(const float* __restrict__ seq,
                         const int* __restrict__ mask) {
    __shared__ unsigned mbits[NCHUNK];
    __shared__ int msum[NCHUNK];
    __shared__ int ssrc[ROWS_PER_BLOCK];
    __shared__ int snv;

    int tid  = threadIdx.x;
    int lane = tid & 31;
    int warp = tid >> 5;

    int b  = blockIdx.x >> 2;                 // 4 blocks per batch
    int d0 = (blockIdx.x & 3) * ROWS_PER_BLOCK;

    // ---- per-block mask scan (512 bits) ----
    #pragma unroll
    for (int r = 0; r < 2; r++) {
        int chunk = warp * 2 + r;
        int s = chunk * 32 + lane;
        int m = (mask[b * SS_ + s] != 0);
        unsigned bal = __ballot_sync(0xffffffffu, m);
        if (lane == 0) mbits[chunk] = bal;
    }
    __syncthreads();
    if (tid < NCHUNK) {
        int v = __popc(mbits[tid]);
        #pragma unroll
        for (int off = 1; off < NCHUNK; off <<= 1) {
            int u = __shfl_up_sync(0x0000ffffu, v, off);
            if (tid >= off) v += u;
        }
        msum[tid] = v;
        if (tid == NCHUNK - 1) snv = v;
    }
    __syncthreads();
    int nv = snv;
    if (d0 == 0 && tid == 0) g_nvalid[b] = nv;

    int nrow = nv - d0;
    if (nrow <= 0) return;                    // kernel 2 handles invalid rows
    if (nrow > ROWS_PER_BLOCK) nrow = ROWS_PER_BLOCK;

    // ---- source index for this block's (valid) rows ----
    if (tid < ROWS_PER_BLOCK) {
        int d = d0 + tid;
        int src = 0;
        if (d < nv) {
            int c = 0, base = 0;
            #pragma unroll
            for (int cc = 0; cc < NCHUNK - 1; cc++)
                if (msum[cc] <= d) { c = cc + 1; base = msum[cc]; }
            unsigned wv = mbits[c];
            int rr = d - base;
            for (int t = 0; t < rr; t++) wv &= wv - 1;
            src = c * 32 + (__ffs(wv) - 1);
        }
        ssrc[tid] = src;
    }
    __syncthreads();

    // ---- load this thread's W slice into registers (once) ----
    u64 w[4][5];
    {
        const u64* wp = g_Wpack + (size_t)tid * 4 * 5;   // k0 = 4*tid
        #pragma unroll
        for (int kk = 0; kk < 4; kk++)
            #pragma unroll
            for (int jp = 0; jp < 5; jp++)
                w[kk][jp] = wp[kk * 5 + jp];
    }

    // x base for this thread: float4 index (warp*32 + lane) within a row
    const float4* xbase = (const float4*)seq + (size_t)b * SS_ * 256 + tid;
    u64* pbase = g_part + (size_t)warp * 5 * NR + (b * SS_ + d0);

    float4 xc = __ldcs(&xbase[(size_t)ssrc[0] * 256]);

    for (int i = 0; i < nrow; i++) {
        // prefetch next row while computing this one
        float4 xn = make_float4(0.f, 0.f, 0.f, 0.f);
        if (i + 1 < nrow) xn = __ldcs(&xbase[(size_t)ssrc[i + 1] * 256]);

        u64 acc[5];
        u64 xx;
        xx = pack2(xc.x, xc.x);
        #pragma unroll
        for (int jp = 0; jp < 5; jp++) acc[jp] = fma2(xx, w[0][jp], 0ull);
        xx = pack2(xc.y, xc.y);
        #pragma unroll
        for (int jp = 0; jp < 5; jp++) acc[jp] = fma2(xx, w[1][jp], acc[jp]);
        xx = pack2(xc.z, xc.z);
        #pragma unroll
        for (int jp = 0; jp < 5; jp++) acc[jp] = fma2(xx, w[2][jp], acc[jp]);
        xx = pack2(xc.w, xc.w);
        #pragma unroll
        for (int jp = 0; jp < 5; jp++) acc[jp] = fma2(xx, w[3][jp], acc[jp]);

        // butterfly reduce across the warp (5 independent f32x2 chains)
        #pragma unroll
        for (int jp = 0; jp < 5; jp++) {
            u64 a = acc[jp];
            #pragma unroll
            for (int off = 16; off >= 1; off >>= 1)
                a = add2(a, __shfl_xor_sync(0xffffffffu, a, off));
            acc[jp] = a;
        }

        // lanes 0..4 store the 5 pair-partials for this (row, warp-slice)
        if (lane < 5) {
            u64 v = (lane == 0) ? acc[0] :
                    (lane == 1) ? acc[1] :
                    (lane == 2) ? acc[2] :
                    (lane == 3) ? acc[3] : acc[4];
            pbase[(size_t)lane * NR + i] = v;
        }
        xc = xn;
    }
}

// ---------------------------------------------------------------------------
// Kernel 2: per-row reduce across 8 k-slices + bias + softmax.
// Invalid rows (d >= nv) get softmax(bias).
// ---------------------------------------------------------------------------
__global__ __launch_bounds__(TPB)
void finalize_kernel(const float* __restrict__ bias,
                     float* __restrict__ out) {
    int r = blockIdx.x * TPB + threadIdx.x;   // 0..32767
    int b = r >> 9;
    int d = r & 511;
    int nv = g_nvalid[b];

    float l[LL_];
    #pragma unroll
    for (int j = 0; j < LL_; j++) l[j] = __ldg(&bias[j]);

    if (d < nv) {
        u64 s[5];
        #pragma unroll
        for (int jp = 0; jp < 5; jp++) s[jp] = g_part[(size_t)jp * NR + r];
        #pragma unroll
        for (int sl = 1; sl < 8; sl++)
            #pragma unroll
            for (int jp = 0; jp < 5; jp++)
                s[jp] = add2(s[jp], g_part[((size_t)sl * 5 + jp) * NR + r]);
        float lo, hi;
        unpack2(lo, hi, s[0]); l[0] += lo; l[1] += hi;
        unpack2(lo, hi, s[1]); l[2] += lo; l[3] += hi;
        unpack2(lo, hi, s[2]); l[4] += lo; l[5] += hi;
        unpack2(lo, hi, s[3]); l[6] += lo; l[7] += hi;
        unpack2(lo, hi, s[4]); l[8] += lo;
    }

    float mx = -3.402823466e+38f;
    #pragma unroll
    for (int j = 0; j < LL_; j++) mx = fmaxf(mx, l[j]);
    float ssum = 0.0f;
    #pragma unroll
    for (int j = 0; j < LL_; j++) { l[j] = __expf(l[j] - mx); ssum += l[j]; }
    float inv = __fdividef(1.0f, ssum);
    float* o = out + (size_t)r * LL_;
    #pragma unroll
    for (int j = 0; j < LL_; j++) o[j] = l[j] * inv;
}

// ---------------------------------------------------------------------------
extern "C" void kernel_launch(void* const* d_in, const int* in_sizes, int n_in,
                              void* d_out, int out_size) {
    const float* seq  = (const float*)d_in[0];   // [B,S,H] f32
    const int*   mask = (const int*)d_in[1];     // [B,S]   i32
    const float* W    = (const float*)d_in[2];   // [H,L]   f32
    const float* bias = (const float*)d_in[3];   // [L]     f32
    float* out = (float*)d_out;                  // [B,S,L] f32

    pack_W<<<HH_ / 256, 256>>>(W);

    gemv_partial_kernel<<<BB_ * (SS_ / ROWS_PER_BLOCK), TPB>>>(seq, mask);  // 256 blocks

    finalize_kernel<<<NR / TPB, TPB>>>(bias, out);                          // 128 blocks
}

// round 13
// speedup vs baseline: 3.1683x; 3.1683x over previous
#include <cuda_runtime.h>
#include <cuda_bf16.h>
#include <cstdint>

// Problem shape (fixed)
#define BB_ 64
#define SS_ 512
#define HH_ 1024
#define LL_ 9

#define TPB 256
#define WARPS 8
#define ROWS_PER_BLOCK 32
#define NCHUNK 16               // 512/32 mask chunks

typedef unsigned long long u64;

// W packed per k as 6 u64 (48 B, 16-aligned): jp0..3 = (W[k][2jp],W[k][2jp+1]),
// jp4 = (W[k][8], 0), slot5 = 0 pad.
__device__ u64 g_Wpack6[HH_ * 6];

__device__ __forceinline__ u64 fma2(u64 a, u64 b, u64 c) {
    u64 d;
    asm("fma.rn.f32x2 %0, %1, %2, %3;" : "=l"(d) : "l"(a), "l"(b), "l"(c));
    return d;
}
__device__ __forceinline__ u64 add2(u64 a, u64 b) {
    u64 d;
    asm("add.rn.f32x2 %0, %1, %2;" : "=l"(d) : "l"(a), "l"(b));
    return d;
}
__device__ __forceinline__ u64 pack2(float lo, float hi) {
    u64 d;
    asm("mov.b64 %0, {%1, %2};" : "=l"(d) : "f"(lo), "f"(hi));
    return d;
}
__device__ __forceinline__ void unpack2(float& lo, float& hi, u64 v) {
    asm("mov.b64 {%0, %1}, %2;" : "=f"(lo), "=f"(hi) : "l"(v));
}

// ---------------------------------------------------------------------------
// One-shot: W [H,L] -> g_Wpack6
// ---------------------------------------------------------------------------
__global__ void pack_W6(const float* __restrict__ W) {
    int k = blockIdx.x * 256 + threadIdx.x;   // 0..1023
    #pragma unroll
    for (int jp = 0; jp < 4; jp++)
        g_Wpack6[k * 6 + jp] = pack2(W[k * LL_ + 2 * jp], W[k * LL_ + 2 * jp + 1]);
    g_Wpack6[k * 6 + 4] = pack2(W[k * LL_ + 8], 0.0f);
    g_Wpack6[k * 6 + 5] = 0ull;
}

// ---------------------------------------------------------------------------
// Per-k compute: broadcast W from smem, two rows (A,B) per lane.
// ---------------------------------------------------------------------------
__device__ __forceinline__ void step_k(float xa, float xb, int k, const u64* sW6,
                                       u64 accA[5], u64 accB[5]) {
    const ulonglong2* wp = (const ulonglong2*)(sW6 + (size_t)k * 6);
    ulonglong2 w01 = wp[0];
    ulonglong2 w23 = wp[1];
    u64 w4 = sW6[k * 6 + 4];
    u64 xxA = pack2(xa, xa);
    u64 xxB = pack2(xb, xb);
    accA[0] = fma2(xxA, w01.x, accA[0]);
    accA[1] = fma2(xxA, w01.y, accA[1]);
    accA[2] = fma2(xxA, w23.x, accA[2]);
    accA[3] = fma2(xxA, w23.y, accA[3]);
    accA[4] = fma2(xxA, w4,    accA[4]);
    accB[0] = fma2(xxB, w01.x, accB[0]);
    accB[1] = fma2(xxB, w01.y, accB[1]);
    accB[2] = fma2(xxB, w23.x, accB[2]);
    accB[3] = fma2(xxB, w23.y, accB[3]);
    accB[4] = fma2(xxB, w4,    accB[4]);
}

// ---------------------------------------------------------------------------
// Main kernel. Block = 32 rows of one batch. Warp w owns k-chunk [128w,128w+128).
// Lane pair (2r, 2r+1) owns rows r and r+16 (parity splits k within the pair).
// No warp reduction: one shfl_xor(1) at the end. W broadcast from smem.
// ---------------------------------------------------------------------------
extern __shared__ u64 dynsm[];
// [0, 6144)        : sW6 (49152 B)
// [6144, 7424)     : part[warp(8)][row(32)][jp(5)] u64 (10240 B)

__global__ __launch_bounds__(TPB, 2)
void bertner_main_kernel(const float* __restrict__ seq,
                         const int* __restrict__ mask,
                         const float* __restrict__ bias,
                         float* __restrict__ out) {
    u64* sW6  = dynsm;
    u64* part = dynsm + HH_ * 6;

    __shared__ unsigned mbits[NCHUNK];
    __shared__ int msum[NCHUNK];
    __shared__ int ssrc[ROWS_PER_BLOCK];
    __shared__ int snv;
    __shared__ float sb[LL_];

    int tid  = threadIdx.x;
    int lane = tid & 31;
    int warp = tid >> 5;

    int b  = blockIdx.x >> 4;                 // 16 blocks per batch
    int d0 = (blockIdx.x & 15) * ROWS_PER_BLOCK;

    if (tid < LL_) sb[tid] = bias[tid];

    // ---- per-block mask scan (512 bits) ----
    #pragma unroll
    for (int r = 0; r < 2; r++) {
        int chunk = warp * 2 + r;
        int s = chunk * 32 + lane;
        int m = (mask[b * SS_ + s] != 0);
        unsigned bal = __ballot_sync(0xffffffffu, m);
        if (lane == 0) mbits[chunk] = bal;
    }
    __syncthreads();
    if (tid < NCHUNK) {
        int v = __popc(mbits[tid]);
        #pragma unroll
        for (int off = 1; off < NCHUNK; off <<= 1) {
            int u = __shfl_up_sync(0x0000ffffu, v, off);
            if (tid >= off) v += u;
        }
        msum[tid] = v;
        if (tid == NCHUNK - 1) snv = v;
    }
    __syncthreads();
    int nv = snv;

    if (d0 >= nv) {
        // whole block invalid: softmax(bias) for its 32 rows
        if (tid < ROWS_PER_BLOCK) {
            float l[LL_];
            float mx = -3.402823466e+38f;
            #pragma unroll
            for (int j = 0; j < LL_; j++) { l[j] = sb[j]; mx = fmaxf(mx, l[j]); }
            float ssum = 0.0f;
            #pragma unroll
            for (int j = 0; j < LL_; j++) { l[j] = __expf(l[j] - mx); ssum += l[j]; }
            float inv = __fdividef(1.0f, ssum);
            float* o = out + (size_t)(b * SS_ + d0 + tid) * LL_;
            #pragma unroll
            for (int j = 0; j < LL_; j++) o[j] = l[j] * inv;
        }
        return;
    }
    int nrow = nv - d0;
    if (nrow > ROWS_PER_BLOCK) nrow = ROWS_PER_BLOCK;

    // ---- source index for this block's 32 rows ----
    if (tid < ROWS_PER_BLOCK) {
        int d = d0 + tid;
        int src = 0;
        if (d < nv) {
            int c = 0, base = 0;
            #pragma unroll
            for (int cc = 0; cc < NCHUNK - 1; cc++)
                if (msum[cc] <= d) { c = cc + 1; base = msum[cc]; }
            unsigned wv = mbits[c];
            int rr = d - base;
            for (int t = 0; t < rr; t++) wv &= wv - 1;
            src = c * 32 + (__ffs(wv) - 1);
        }
        ssrc[tid] = src;
    }

    // ---- stage packed W into smem (49152 B, coalesced float4 copy) ----
    {
        const float4* g = (const float4*)g_Wpack6;
        float4* dd = (float4*)sW6;
        #pragma unroll
        for (int it = 0; it < (HH_ * 6 * 8 / 16) / TPB; it++)   // 12
            dd[it * TPB + tid] = g[it * TPB + tid];
    }
    __syncthreads();

    // ---- main GEMV: warp k-chunk, lane-pair per row ----
    int p = lane & 1;
    int r = lane >> 1;                        // 0..15
    bool vA = r < nrow;
    bool vB = (r + 16) < nrow;

    const float4* pA = (const float4*)seq + ((size_t)(b * SS_ + ssrc[r]) * 256) + warp * 32;
    const float4* pB = (const float4*)seq + ((size_t)(b * SS_ + ssrc[r + 16]) * 256) + warp * 32;

    float4 z4 = make_float4(0.f, 0.f, 0.f, 0.f);
    float4 cA0 = z4, cA1 = z4, cB0 = z4, cB1 = z4;
    if (vA) { cA0 = __ldcs(pA + p); cA1 = __ldcs(pA + p + 2); }
    if (vB) { cB0 = __ldcs(pB + p); cB1 = __ldcs(pB + p + 2); }

    u64 accA[5], accB[5];
    #pragma unroll
    for (int jp = 0; jp < 5; jp++) { accA[jp] = 0ull; accB[jp] = 0ull; }

    #pragma unroll
    for (int ss = 0; ss < 8; ss++) {
        float4 nA0 = z4, nA1 = z4, nB0 = z4, nB1 = z4;
        if (ss < 7) {
            int o = (ss + 1) * 4 + p;
            if (vA) { nA0 = __ldcs(pA + o); nA1 = __ldcs(pA + o + 2); }
            if (vB) { nB0 = __ldcs(pB + o); nB1 = __ldcs(pB + o + 2); }
        }
        int kb = warp * 128 + ss * 16 + p * 4;
        step_k(cA0.x, cB0.x, kb + 0, sW6, accA, accB);
        step_k(cA0.y, cB0.y, kb + 1, sW6, accA, accB);
        step_k(cA0.z, cB0.z, kb + 2, sW6, accA, accB);
        step_k(cA0.w, cB0.w, kb + 3, sW6, accA, accB);
        step_k(cA1.x, cB1.x, kb + 8, sW6, accA, accB);
        step_k(cA1.y, cB1.y, kb + 9, sW6, accA, accB);
        step_k(cA1.z, cB1.z, kb + 10, sW6, accA, accB);
        step_k(cA1.w, cB1.w, kb + 11, sW6, accA, accB);
        cA0 = nA0; cA1 = nA1; cB0 = nB0; cB1 = nB1;
    }

    // parity combine: partner lane holds the other k-subset of the SAME rows
    #pragma unroll
    for (int jp = 0; jp < 5; jp++) {
        accA[jp] = add2(accA[jp], __shfl_xor_sync(0xffffffffu, accA[jp], 1));
        accB[jp] = add2(accB[jp], __shfl_xor_sync(0xffffffffu, accB[jp], 1));
    }

    // even lane stores both rows' chunk-partials
    if (p == 0) {
        u64* pp = part + (size_t)warp * 160;
        #pragma unroll
        for (int jp = 0; jp < 5; jp++) {
            pp[r * 5 + jp] = accA[jp];
            pp[(r + 16) * 5 + jp] = accB[jp];
        }
    }
    __syncthreads();

    // ---- combine the 8 k-chunks: 160 cells, 8-way sum each ----
    if (tid < 160) {
        u64 s = part[tid];
        #pragma unroll
        for (int w = 1; w < 8; w++) s = add2(s, part[w * 160 + tid]);
        part[tid] = s;
    }
    __syncthreads();

    // ---- epilogue: thread rr < 32 -> row rr (invalid rows have zero sums) ----
    if (tid < ROWS_PER_BLOCK) {
        float l[LL_ + 1];
        float lo, hi;
        unpack2(lo, hi, part[tid * 5 + 0]); l[0] = lo; l[1] = hi;
        unpack2(lo, hi, part[tid * 5 + 1]); l[2] = lo; l[3] = hi;
        unpack2(lo, hi, part[tid * 5 + 2]); l[4] = lo; l[5] = hi;
        unpack2(lo, hi, part[tid * 5 + 3]); l[6] = lo; l[7] = hi;
        unpack2(lo, hi, part[tid * 5 + 4]); l[8] = lo;
        float mx = -3.402823466e+38f;
        #pragma unroll
        for (int j = 0; j < LL_; j++) { l[j] += sb[j]; mx = fmaxf(mx, l[j]); }
        float ssum = 0.0f;
        #pragma unroll
        for (int j = 0; j < LL_; j++) { l[j] = __expf(l[j] - mx); ssum += l[j]; }
        float inv = __fdividef(1.0f, ssum);
        float* o = out + (size_t)(b * SS_ + d0 + tid) * LL_;
        #pragma unroll
        for (int j = 0; j < LL_; j++) o[j] = l[j] * inv;
    }
}

// ---------------------------------------------------------------------------
#define DYN_SMEM ((HH_ * 6 + 8 * 32 * 5) * 8)   // 49152 + 10240 = 59392 B

extern "C" void kernel_launch(void* const* d_in, const int* in_sizes, int n_in,
                              void* d_out, int out_size) {
    const float* seq  = (const float*)d_in[0];   // [B,S,H] f32
    const int*   mask = (const int*)d_in[1];     // [B,S]   i32
    const float* W    = (const float*)d_in[2];   // [H,L]   f32
    const float* bias = (const float*)d_in[3];   // [L]     f32
    float* out = (float*)d_out;                  // [B,S,L] f32

    cudaFuncSetAttribute(bertner_main_kernel,
                         cudaFuncAttributeMaxDynamicSharedMemorySize, DYN_SMEM);

    pack_W6<<<HH_ / 256, 256>>>(W);

    int grid = (BB_ * SS_) / ROWS_PER_BLOCK;     // 1024
    bertner_main_kernel<<<grid, TPB, DYN_SMEM>>>(seq, mask, bias, out);
}